// round 1
// baseline (speedup 1.0000x reference)
#include <cuda_runtime.h>
#include <cstdint>

// y[N] = x[N,H] @ w[H] + bias,  w[h] = FP4_TABLE[codes[h]] * absmax[h>>6]
// N = 32768, H = 4096. Pure HBM-streaming GEMV.

#define H_DIM 4096
#define ROWS_PER_BLOCK 8          // 8 warps * 1 row/warp
#define THREADS (ROWS_PER_BLOCK * 32)

__device__ __constant__ float c_fp4_tab[16] = {
    0.0f, 0.0052083333f, 0.6666667f, 1.0f, 0.3333333f, 0.5f, 0.16666667f, 0.25f,
    -0.0f, -0.0052083333f, -0.6666667f, -1.0f, -0.3333333f, -0.5f, -0.16666667f, -0.25f
};

__global__ __launch_bounds__(THREADS)
void fp4_gemv_kernel(const float* __restrict__ x,
                     const int*   __restrict__ codes,
                     const float* __restrict__ absmax,
                     const float* __restrict__ bias,
                     float*       __restrict__ y,
                     int N)
{
    __shared__ float w_s[H_DIM];

    // Dequantize the (tiny) weight vector into shared memory once per block.
    // codes/absmax are 16KB/256B — L2-resident across all 4096 blocks.
    for (int i = threadIdx.x; i < H_DIM; i += THREADS) {
        w_s[i] = c_fp4_tab[codes[i] & 15] * absmax[i >> 6];
    }
    __syncthreads();

    const int warp = threadIdx.x >> 5;
    const int lane = threadIdx.x & 31;
    const int row  = blockIdx.x * ROWS_PER_BLOCK + warp;
    if (row >= N) return;

    const float4* __restrict__ xr = reinterpret_cast<const float4*>(x + (size_t)row * H_DIM);
    const float4* __restrict__ ws = reinterpret_cast<const float4*>(w_s);

    // H/4 = 1024 float4 per row; each lane does 32 iterations.
    // Unroll 8 -> 8 outstanding 16B loads per thread (MLP to hide DRAM latency).
    float acc = 0.0f;
    #pragma unroll 8
    for (int k = lane; k < H_DIM / 4; k += 32) {
        float4 xv = xr[k];
        float4 wv = ws[k];
        acc = fmaf(xv.x, wv.x, acc);
        acc = fmaf(xv.y, wv.y, acc);
        acc = fmaf(xv.z, wv.z, acc);
        acc = fmaf(xv.w, wv.w, acc);
    }

    // Warp reduction
    #pragma unroll
    for (int off = 16; off > 0; off >>= 1)
        acc += __shfl_xor_sync(0xFFFFFFFFu, acc, off);

    if (lane == 0)
        y[row] = acc + bias[0];
}

extern "C" void kernel_launch(void* const* d_in, const int* in_sizes, int n_in,
                              void* d_out, int out_size)
{
    const float* x      = (const float*)d_in[0];   // [N, H] fp32
    const int*   codes  = (const int*)  d_in[1];   // [1, H] int32
    const float* absmax = (const float*)d_in[2];   // [1, H/64] fp32
    const float* bias   = (const float*)d_in[3];   // [1] fp32
    float*       y      = (float*)d_out;           // [N, 1] fp32

    const int N = in_sizes[0] / H_DIM;             // 32768
    const int grid = (N + ROWS_PER_BLOCK - 1) / ROWS_PER_BLOCK;

    fp4_gemv_kernel<<<grid, THREADS>>>(x, codes, absmax, bias, y, N);
}

// round 3
// speedup vs baseline: 1.0550x; 1.0550x over previous
#include <cuda_runtime.h>
#include <cstdint>

// y[N] = x[N,H] @ w[H] + bias,  w[h] = FP4_TABLE[codes[h]] * absmax[h>>6]
// N = 32768, H = 4096. Pure HBM-streaming GEMV — target is the DRAM roofline.

#define H_DIM 4096
#define ROWS_PER_BLOCK 8          // 8 warps * 1 row/warp
#define THREADS (ROWS_PER_BLOCK * 32)

__device__ __constant__ float c_fp4_tab[16] = {
    0.0f, 0.0052083333f, 0.6666667f, 1.0f, 0.3333333f, 0.5f, 0.16666667f, 0.25f,
    -0.0f, -0.0052083333f, -0.6666667f, -1.0f, -0.3333333f, -0.5f, -0.16666667f, -0.25f
};

__global__ __launch_bounds__(THREADS)
void fp4_gemv_kernel(const float* __restrict__ x,
                     const int*   __restrict__ codes,
                     const float* __restrict__ absmax,
                     const float* __restrict__ bias,
                     float*       __restrict__ y,
                     int N)
{
    __shared__ float w_s[H_DIM];

    // Dequantize the tiny weight vector into shared memory once per block.
    // codes/absmax are 16KB/256B — L2-resident across all blocks.
    for (int i = threadIdx.x; i < H_DIM; i += THREADS) {
        w_s[i] = c_fp4_tab[codes[i] & 15] * absmax[i >> 6];
    }

    const float b = __ldg(bias);   // hoisted: off the epilogue critical path
    __syncthreads();

    const int warp = threadIdx.x >> 5;
    const int lane = threadIdx.x & 31;
    const int row  = blockIdx.x * ROWS_PER_BLOCK + warp;
    if (row >= N) return;

    const float4* __restrict__ xr = reinterpret_cast<const float4*>(x + (size_t)row * H_DIM);
    const float4* __restrict__ ws = reinterpret_cast<const float4*>(w_s);

    // 1024 float4 per row; 32 per lane, processed as 4 groups of 8.
    // Stage all 8 loads of a group into registers BEFORE any FMA so ptxas
    // emits 8 back-to-back LDG.E.128 (MLP=8 per warp; regs ~64 is intended).
    float acc0 = 0.0f, acc1 = 0.0f;

    #pragma unroll
    for (int g = 0; g < 4; g++) {
        float4 xv[8];
        #pragma unroll
        for (int j = 0; j < 8; j++) {
            xv[j] = __ldcs(&xr[g * 256 + j * 32 + lane]);   // evict-first: x is read-once
        }
        #pragma unroll
        for (int j = 0; j < 8; j++) {
            float4 wv = ws[g * 256 + j * 32 + lane];
            acc0 = fmaf(xv[j].x, wv.x, acc0);
            acc1 = fmaf(xv[j].y, wv.y, acc1);
            acc0 = fmaf(xv[j].z, wv.z, acc0);
            acc1 = fmaf(xv[j].w, wv.w, acc1);
        }
    }
    float acc = acc0 + acc1;

    // Warp reduction
    #pragma unroll
    for (int off = 16; off > 0; off >>= 1)
        acc += __shfl_xor_sync(0xFFFFFFFFu, acc, off);

    if (lane == 0)
        y[row] = acc + b;
}

extern "C" void kernel_launch(void* const* d_in, const int* in_sizes, int n_in,
                              void* d_out, int out_size)
{
    const float* x      = (const float*)d_in[0];   // [N, H] fp32
    const int*   codes  = (const int*)  d_in[1];   // [1, H] int32
    const float* absmax = (const float*)d_in[2];   // [1, H/64] fp32
    const float* bias   = (const float*)d_in[3];   // [1] fp32
    float*       y      = (float*)d_out;           // [N, 1] fp32

    const int N = in_sizes[0] / H_DIM;             // 32768
    const int grid = (N + ROWS_PER_BLOCK - 1) / ROWS_PER_BLOCK;

    fp4_gemv_kernel<<<grid, THREADS>>>(x, codes, absmax, bias, y, N);
}